// round 8
// baseline (speedup 1.0000x reference)
#include <cuda_runtime.h>
#include <cstdint>

// IDWT (inverse Haar wavelet). Inputs LL,LH,HL,HH: [B=16,C=64,h=128,w=128] f32.
// Output: [B,C,256,256] f32. Closed-form 2x2 butterfly, s^2 = 0.5.
//
// Warp-owns-row variant: each warp produces one FULL output row pair
// (2 x 256 floats). Lane L handles output float4 columns L and L+32.
// Loads: 8 front-batched LDG.64, each instr 256B warp-contiguous.
// Stores: 4 STG.128, each instr 512B warp-contiguous; the warp's stores
// cover two complete 1KB output rows.

static constexpr int NROWS = 16 * 64 * 128;   // B*C*h = 131072 (one warp each)
static constexpr int BLOCK = 256;             // 8 warps -> 8 input rows per CTA
static constexpr int NBLOCKS = NROWS / 8;     // 16384

__global__ __launch_bounds__(BLOCK) void idwt_haar_kernel(
    const float2* __restrict__ LL,
    const float2* __restrict__ LH,
    const float2* __restrict__ HL,
    const float2* __restrict__ HH,
    float4* __restrict__ out)
{
    int warp = (blockIdx.x << 3) + (threadIdx.x >> 5);  // input row id = bc*128 + i
    int lane = threadIdx.x & 31;

    int base = (warp << 6) + lane;       // float2 index of first column
    int q0 = base;                       // col c = lane
    int q1 = base + 32;                  // col c = lane + 32

    float2 ll0 = __ldcs(&LL[q0]);
    float2 lh0 = __ldcs(&LH[q0]);
    float2 hl0 = __ldcs(&HL[q0]);
    float2 hh0 = __ldcs(&HH[q0]);
    float2 ll1 = __ldcs(&LL[q1]);
    float2 lh1 = __ldcs(&LH[q1]);
    float2 hl1 = __ldcs(&HL[q1]);
    float2 hh1 = __ldcs(&HH[q1]);

    int bc = warp >> 7;
    int i  = warp & 127;

    // output [bc][256][256] f32 -> float4 row stride 64
    size_t otop = ((size_t)bc * 256 + 2 * i) * 64 + (size_t)lane;

    float4 t0, b0, t1, b1;
    {
        float s0 = ll0.x + hh0.x, d0 = ll0.x - hh0.x;
        float s1 = lh0.x + hl0.x, d1 = lh0.x - hl0.x;
        t0.x = 0.5f * (s0 - s1);
        t0.y = 0.5f * (d0 + d1);
        b0.x = 0.5f * (d0 - d1);
        b0.y = 0.5f * (s0 + s1);
        s0 = ll0.y + hh0.y; d0 = ll0.y - hh0.y;
        s1 = lh0.y + hl0.y; d1 = lh0.y - hl0.y;
        t0.z = 0.5f * (s0 - s1);
        t0.w = 0.5f * (d0 + d1);
        b0.z = 0.5f * (d0 - d1);
        b0.w = 0.5f * (s0 + s1);
    }
    {
        float s0 = ll1.x + hh1.x, d0 = ll1.x - hh1.x;
        float s1 = lh1.x + hl1.x, d1 = lh1.x - hl1.x;
        t1.x = 0.5f * (s0 - s1);
        t1.y = 0.5f * (d0 + d1);
        b1.x = 0.5f * (d0 - d1);
        b1.y = 0.5f * (s0 + s1);
        s0 = ll1.y + hh1.y; d0 = ll1.y - hh1.y;
        s1 = lh1.y + hl1.y; d1 = lh1.y - hl1.y;
        t1.z = 0.5f * (s0 - s1);
        t1.w = 0.5f * (d0 + d1);
        b1.z = 0.5f * (d0 - d1);
        b1.w = 0.5f * (s0 + s1);
    }

    __stcs(&out[otop], t0);
    __stcs(&out[otop + 32], t1);
    __stcs(&out[otop + 64], b0);
    __stcs(&out[otop + 96], b1);
}

extern "C" void kernel_launch(void* const* d_in, const int* in_sizes, int n_in,
                              void* d_out, int out_size)
{
    const float2* LL = (const float2*)d_in[0];
    const float2* LH = (const float2*)d_in[1];
    const float2* HL = (const float2*)d_in[2];
    const float2* HH = (const float2*)d_in[3];

    float4* out = (float4*)d_out;

    idwt_haar_kernel<<<NBLOCKS, BLOCK>>>(LL, LH, HL, HH, out);
}

// round 9
// speedup vs baseline: 1.0055x; 1.0055x over previous
#include <cuda_runtime.h>
#include <cstdint>

// IDWT (inverse Haar wavelet). Inputs LL,LH,HL,HH: [B=16,C=64,h=128,w=128] f32.
// Output: [B,C,256,256] f32. Closed-form 2x2 butterfly, s^2 = 0.5.
//
// Final kernel (best of session): one thread per output float4-column pair.
// Loads one float2 per band (warp-contiguous 256B per load instr), writes one
// float4 to output row 2i and one to row 2i+1 (warp-contiguous 512B per store
// instr). 20 regs, occ ~83%, DRAM ~83% of peak = turnaround-limited plateau.

static constexpr int C2 = 64;                       // float2s per input row
static constexpr int NROWS = 16 * 64 * 128;         // B*C*h = 131072
static constexpr int NTHREADS_TOTAL = NROWS * C2;   // 8,388,608
static constexpr int BLOCK = 256;

__global__ __launch_bounds__(BLOCK) void idwt_haar_kernel(
    const float2* __restrict__ LL,
    const float2* __restrict__ LH,
    const float2* __restrict__ HL,
    const float2* __restrict__ HH,
    float4* __restrict__ out)
{
    int tid = blockIdx.x * BLOCK + threadIdx.x;   // grid covers domain exactly

    // input float2 index == tid  (row-major [NROWS, 64])
    float2 ll = __ldcs(&LL[tid]);
    float2 lh = __ldcs(&LH[tid]);
    float2 hl = __ldcs(&HL[tid]);
    float2 hh = __ldcs(&HH[tid]);

    int row = tid >> 6;        // bc*128 + i
    int c   = tid & 63;        // output float4 column index

    int bc = row >> 7;
    int i  = row & 127;

    // output [bc][256][256] f32 -> float4 row stride 64
    size_t obase = ((size_t)bc * 256 + 2 * i) * 64 + (size_t)c;

    float4 t, b;
    {
        float s0 = ll.x + hh.x, d0 = ll.x - hh.x;
        float s1 = lh.x + hl.x, d1 = lh.x - hl.x;
        t.x = 0.5f * (s0 - s1);
        t.y = 0.5f * (d0 + d1);
        b.x = 0.5f * (d0 - d1);
        b.y = 0.5f * (s0 + s1);
    }
    {
        float s0 = ll.y + hh.y, d0 = ll.y - hh.y;
        float s1 = lh.y + hl.y, d1 = lh.y - hl.y;
        t.z = 0.5f * (s0 - s1);
        t.w = 0.5f * (d0 + d1);
        b.z = 0.5f * (d0 - d1);
        b.w = 0.5f * (s0 + s1);
    }

    __stcs(&out[obase], t);
    __stcs(&out[obase + 64], b);
}

extern "C" void kernel_launch(void* const* d_in, const int* in_sizes, int n_in,
                              void* d_out, int out_size)
{
    const float2* LL = (const float2*)d_in[0];
    const float2* LH = (const float2*)d_in[1];
    const float2* HL = (const float2*)d_in[2];
    const float2* HH = (const float2*)d_in[3];

    float4* out = (float4*)d_out;

    int blocks = NTHREADS_TOTAL / BLOCK;  // 32768
    idwt_haar_kernel<<<blocks, BLOCK>>>(LL, LH, HL, HH, out);
}